// round 1
// baseline (speedup 1.0000x reference)
#include <cuda_runtime.h>
#include <cuda_bf16.h>
#include <cstdint>
#include <cstdio>

// ---------------- problem constants ----------------
#define NN 50000
#define EE 500000
#define GG 64

// ---------------- scratch (device globals; no allocation allowed) ----------
__device__ float g_t1[(size_t)EE * 256];     // 512 MB  edge intermediate 1
__device__ float g_t2[(size_t)EE * 256];     // 512 MB  edge intermediate 2
__device__ float g_hA[(size_t)NN * 256];     // node features ping
__device__ float g_hB[(size_t)NN * 256];     // node features pong
__device__ float g_stats[1024];              // sum1[256], sq1[256], sum2[256], sq2[256]
__device__ float g_norm[1024];               // a1[256], c1[256], a2[256], c2[256]
__device__ int   g_deg[NN];
__device__ int   g_rowptr[NN + 1];
__device__ int   g_cursor[NN];
__device__ int   g_eidx[EE];
__device__ int   g_cnt[GG];
__device__ int   g_gstart[GG + 1];
__device__ float g_pool[GG * 256];
__device__ float g_zbuf[GG * 128];

// ---------------- CSR build ----------------
__global__ void hist_deg_kernel(const int* __restrict__ dst, int* __restrict__ deg, int E) {
    int e = blockIdx.x * blockDim.x + threadIdx.x;
    if (e < E) atomicAdd(&deg[dst[e]], 1);
}

__global__ void hist_cnt_kernel(const int* __restrict__ batch, int* __restrict__ cnt, int n) {
    int i = blockIdx.x * blockDim.x + threadIdx.x;
    if (i < n) atomicAdd(&cnt[batch[i]], 1);
}

__global__ void scan_kernel(const int* __restrict__ deg, int* __restrict__ rowptr,
                            int* __restrict__ cursor, const int* __restrict__ cnt,
                            int* __restrict__ gstart, int n) {
    __shared__ int sh[1024];
    __shared__ int carry;
    int t = threadIdx.x;
    if (t == 0) carry = 0;
    __syncthreads();
    for (int base = 0; base < n; base += 1024) {
        int idx = base + t;
        int v = (idx < n) ? deg[idx] : 0;
        sh[t] = v;
        __syncthreads();
        for (int off = 1; off < 1024; off <<= 1) {
            int add = (t >= off) ? sh[t - off] : 0;
            __syncthreads();
            sh[t] += add;
            __syncthreads();
        }
        int ex = sh[t] - v;
        int cbase = carry;
        if (idx < n) { rowptr[idx] = cbase + ex; cursor[idx] = cbase + ex; }
        __syncthreads();
        if (t == 1023) carry = cbase + sh[1023];
        __syncthreads();
    }
    if (t == 0) {
        rowptr[n] = carry;
        int s = 0;
        for (int g = 0; g < GG; g++) { gstart[g] = s; s += cnt[g]; }
        gstart[GG] = s;
    }
}

__global__ void fill_csr_kernel(const int* __restrict__ dst, int* __restrict__ cursor,
                                int* __restrict__ eidx, int E) {
    int e = blockIdx.x * blockDim.x + threadIdx.x;
    if (e < E) {
        int p = atomicAdd(&cursor[dst[e]], 1);
        eidx[p] = e;
    }
}

// ---------------- fused GEMM (+ per-channel BN stats) ----------------
// GATHER=true : A row e = [feat[dst[e]] , feat[src[e]] - feat[dst[e]]]  (C channels each, K = 2C)
// GATHER=false: A row e = relu(t_in[e,:] * a + c)                       (K channels)
template <int K, int C, int OC, bool GATHER>
__global__ __launch_bounds__(256)
void gemm_kernel(const float* __restrict__ feats,
                 const int* __restrict__ src, const int* __restrict__ dst,
                 const float* __restrict__ a, const float* __restrict__ c,
                 const float* __restrict__ W, const float* __restrict__ bias,
                 float* __restrict__ out,
                 float* __restrict__ stat_sum, float* __restrict__ stat_sq,
                 int E) {
    constexpr int TM = 128, TN = 64, TK = 16;
    __shared__ float As[TK][TM + 4];
    __shared__ float Bs[TK][TN + 4];
    __shared__ int sdst[TM], ssrc[TM];
    __shared__ float s_sum[TN], s_sq[TN];

    const int tid = threadIdx.x;
    const int e0 = blockIdx.x * TM;
    const int col0 = blockIdx.y * TN;
    const int tx = tid & 15, ty = tid >> 4;

    if (GATHER) {
        if (tid < TM) {
            int e = e0 + tid;
            int ee = (e < E) ? e : (E - 1);
            sdst[tid] = dst[ee];
            ssrc[tid] = src[ee];
        }
    }
    if (tid < TN) { s_sum[tid] = 0.f; s_sq[tid] = 0.f; }

    float acc[8][4];
#pragma unroll
    for (int i = 0; i < 8; i++)
#pragma unroll
        for (int j = 0; j < 4; j++) acc[i][j] = 0.f;

    for (int k0 = 0; k0 < K; k0 += TK) {
        __syncthreads();
        // ---- load A tile (128 rows x 16 k) ----
        {
            int kk = tid & 15;
            int r0 = tid >> 4;
            int k = k0 + kk;
#pragma unroll
            for (int i = 0; i < 8; i++) {
                int r = r0 + i * 16;
                float v = 0.f;
                if (GATHER) {
                    if (k < K) {
                        int nd = sdst[r];
                        if (k < C) {
                            v = feats[nd * C + k];
                        } else {
                            int kc = k - C;
                            v = feats[ssrc[r] * C + kc] - feats[nd * C + kc];
                        }
                    }
                } else {
                    int e = e0 + r;
                    if (e < E) {
                        float t = feats[(size_t)e * K + k];
                        v = fmaxf(t * a[k] + c[k], 0.f);
                    }
                }
                As[kk][r] = v;
            }
        }
        // ---- load B tile (16 k x 64 cols) ----
        {
            int colb = tid & 63;
            int kk0 = tid >> 6;
#pragma unroll
            for (int i = 0; i < 4; i++) {
                int kk = kk0 + i * 4;
                int k = k0 + kk;
                Bs[kk][colb] = (k < K) ? W[(size_t)k * OC + col0 + colb] : 0.f;
            }
        }
        __syncthreads();
        // ---- compute ----
#pragma unroll
        for (int kk = 0; kk < TK; kk++) {
            float af[8], bf[4];
#pragma unroll
            for (int i = 0; i < 8; i++) af[i] = As[kk][ty * 8 + i];
#pragma unroll
            for (int j = 0; j < 4; j++) bf[j] = Bs[kk][tx * 4 + j];
#pragma unroll
            for (int i = 0; i < 8; i++)
#pragma unroll
                for (int j = 0; j < 4; j++) acc[i][j] += af[i] * bf[j];
        }
    }

    // ---- epilogue: bias, store, per-column stats ----
    const int colbase = col0 + tx * 4;
    float psum[4] = {0, 0, 0, 0}, psq[4] = {0, 0, 0, 0};
#pragma unroll
    for (int i = 0; i < 8; i++) {
        int e = e0 + ty * 8 + i;
        if (e < E) {
            float v0 = acc[i][0] + bias[colbase + 0];
            float v1 = acc[i][1] + bias[colbase + 1];
            float v2 = acc[i][2] + bias[colbase + 2];
            float v3 = acc[i][3] + bias[colbase + 3];
            psum[0] += v0; psq[0] += v0 * v0;
            psum[1] += v1; psq[1] += v1 * v1;
            psum[2] += v2; psq[2] += v2 * v2;
            psum[3] += v3; psq[3] += v3 * v3;
            *reinterpret_cast<float4*>(&out[(size_t)e * OC + colbase]) =
                make_float4(v0, v1, v2, v3);
        }
    }
#pragma unroll
    for (int j = 0; j < 4; j++) {
        atomicAdd(&s_sum[tx * 4 + j], psum[j]);
        atomicAdd(&s_sq[tx * 4 + j], psq[j]);
    }
    __syncthreads();
    if (tid < TN) {
        atomicAdd(&stat_sum[col0 + tid], s_sum[tid]);
        atomicAdd(&stat_sq[col0 + tid], s_sq[tid]);
    }
}

// ---------------- BN finalize: a = g*rsqrt(var+eps), c = beta - mean*a --------
__global__ void finalize_kernel(const float* __restrict__ sum, const float* __restrict__ sq,
                                const float* __restrict__ gamma, const float* __restrict__ beta,
                                float* __restrict__ a, float* __restrict__ c,
                                int OC, float invE) {
    int i = blockIdx.x * blockDim.x + threadIdx.x;
    if (i < OC) {
        float m = sum[i] * invE;
        float var = sq[i] * invE - m * m;
        float rs = rsqrtf(var + 1e-5f);
        float ai = gamma[i] * rs;
        a[i] = ai;
        c[i] = beta[i] - m * ai;
    }
}

// ---------------- normalize + relu + mean-aggregate (CSR, warp per node) -----
template <int OC>
__global__ __launch_bounds__(256)
void aggregate_kernel(const float* __restrict__ t, const int* __restrict__ rowptr,
                      const int* __restrict__ eidx, const float* __restrict__ a,
                      const float* __restrict__ c, float* __restrict__ hout, int n) {
    int warp = (blockIdx.x * blockDim.x + threadIdx.x) >> 5;
    int lane = threadIdx.x & 31;
    if (warp >= n) return;
    constexpr int R = OC / 32;
    float av[R], cv[R], acc[R];
#pragma unroll
    for (int j = 0; j < R; j++) {
        int ch = j * 32 + lane;
        av[j] = a[ch];
        cv[j] = c[ch];
        acc[j] = 0.f;
    }
    int beg = rowptr[warp], end = rowptr[warp + 1];
    for (int p = beg; p < end; p++) {
        int e = eidx[p];
        const float* row = t + (size_t)e * OC;
#pragma unroll
        for (int j = 0; j < R; j++) {
            float v = row[j * 32 + lane];
            acc[j] += fmaxf(v * av[j] + cv[j], 0.f);
        }
    }
    float inv = 1.f / fmaxf((float)(end - beg), 1.f);
#pragma unroll
    for (int j = 0; j < R; j++) hout[(size_t)warp * OC + j * 32 + lane] = acc[j] * inv;
}

// ---------------- global mean pool per graph ----------------
__global__ void pool_kernel(const float* __restrict__ h, const int* __restrict__ gstart,
                            float* __restrict__ pool) {
    int g = blockIdx.x;
    int ch = threadIdx.x;  // 256 threads
    int beg = gstart[g], end = gstart[g + 1];
    float s = 0.f;
    for (int nidx = beg; nidx < end; nidx++) s += h[(size_t)nidx * 256 + ch];
    pool[g * 256 + ch] = s / fmaxf((float)(end - beg), 1.f);
}

// ---------------- head ----------------
__global__ void head1_kernel(const float* __restrict__ pool, const float* __restrict__ W,
                             const float* __restrict__ b, float* __restrict__ z) {
    int g = blockIdx.x, j = threadIdx.x;  // 128 threads
    __shared__ float sp[256];
    sp[j] = pool[g * 256 + j];
    sp[j + 128] = pool[g * 256 + j + 128];
    __syncthreads();
    float s = b[j];
#pragma unroll 8
    for (int k = 0; k < 256; k++) s += sp[k] * W[k * 128 + j];
    z[g * 128 + j] = fmaxf(s, 0.f);
}

__global__ void head2_kernel(const float* __restrict__ z, const float* __restrict__ W,
                             const float* __restrict__ b, float* __restrict__ out) {
    int t = threadIdx.x;  // 128 threads: (g, j)
    int g = t >> 1, j = t & 1;
    float s = b[j];
#pragma unroll 8
    for (int k = 0; k < 128; k++) s += z[g * 128 + k] * W[k * 2 + j];
    out[g * 2 + j] = s;
}

// ---------------- launch ----------------
extern "C" void kernel_launch(void* const* d_in, const int* in_sizes, int n_in,
                              void* d_out, int out_size) {
    const float* x     = (const float*)d_in[0];
    const int*   ei    = (const int*)d_in[1];
    const int*   batch = (const int*)d_in[2];

    const int E = in_sizes[1] / 2;
    const int n = in_sizes[2];
    const int* srcp = ei;
    const int* dstp = ei + E;

    // weights in metadata order
    const float* W[3][2];  const float* B[3][2];
    const float* Gm[3][2]; const float* Bt[3][2];
    for (int l = 0; l < 3; l++) {
        int base = 3 + l * 8;
        W[l][0]  = (const float*)d_in[base + 0];
        B[l][0]  = (const float*)d_in[base + 1];
        Gm[l][0] = (const float*)d_in[base + 2];
        Bt[l][0] = (const float*)d_in[base + 3];
        W[l][1]  = (const float*)d_in[base + 4];
        B[l][1]  = (const float*)d_in[base + 5];
        Gm[l][1] = (const float*)d_in[base + 6];
        Bt[l][1] = (const float*)d_in[base + 7];
    }
    const float* hW1 = (const float*)d_in[27];
    const float* hb1 = (const float*)d_in[28];
    const float* hW2 = (const float*)d_in[29];
    const float* hb2 = (const float*)d_in[30];

    // scratch addresses
    float *t1, *t2, *hA, *hB, *stats, *norm, *pool, *zbuf;
    int *deg, *rowptr, *cursor, *eidx, *cnt, *gstart;
    cudaGetSymbolAddress((void**)&t1, g_t1);
    cudaGetSymbolAddress((void**)&t2, g_t2);
    cudaGetSymbolAddress((void**)&hA, g_hA);
    cudaGetSymbolAddress((void**)&hB, g_hB);
    cudaGetSymbolAddress((void**)&stats, g_stats);
    cudaGetSymbolAddress((void**)&norm, g_norm);
    cudaGetSymbolAddress((void**)&deg, g_deg);
    cudaGetSymbolAddress((void**)&rowptr, g_rowptr);
    cudaGetSymbolAddress((void**)&cursor, g_cursor);
    cudaGetSymbolAddress((void**)&eidx, g_eidx);
    cudaGetSymbolAddress((void**)&cnt, g_cnt);
    cudaGetSymbolAddress((void**)&gstart, g_gstart);
    cudaGetSymbolAddress((void**)&pool, g_pool);
    cudaGetSymbolAddress((void**)&zbuf, g_zbuf);

    float* sum1 = stats + 0;   float* sq1 = stats + 256;
    float* sum2 = stats + 512; float* sq2 = stats + 768;
    float* a1 = norm + 0;   float* c1 = norm + 256;
    float* a2 = norm + 512; float* c2 = norm + 768;

    const float invE = 1.f / (float)E;
    const int EB = (E + 127) / 128;
    const int EG = (E + 255) / 256;
    const int NG = (n + 255) / 256;
    const int AGG = (n * 32 + 255) / 256;

    // ---- CSR build ----
    cudaMemsetAsync(deg, 0, n * sizeof(int));
    cudaMemsetAsync(cnt, 0, GG * sizeof(int));
    hist_deg_kernel<<<EG, 256>>>(dstp, deg, E);
    hist_cnt_kernel<<<NG, 256>>>(batch, cnt, n);
    scan_kernel<<<1, 1024>>>(deg, rowptr, cursor, cnt, gstart, n);
    fill_csr_kernel<<<EG, 256>>>(dstp, cursor, eidx, E);

    // ---- layer 1: 7 -> 64 ----
    cudaMemsetAsync(stats, 0, 1024 * sizeof(float));
    gemm_kernel<14, 7, 64, true><<<dim3(EB, 1), 256>>>(
        x, srcp, dstp, nullptr, nullptr, W[0][0], B[0][0], t1, sum1, sq1, E);
    finalize_kernel<<<1, 64>>>(sum1, sq1, Gm[0][0], Bt[0][0], a1, c1, 64, invE);
    gemm_kernel<64, 0, 64, false><<<dim3(EB, 1), 256>>>(
        t1, nullptr, nullptr, a1, c1, W[0][1], B[0][1], t2, sum2, sq2, E);
    finalize_kernel<<<1, 64>>>(sum2, sq2, Gm[0][1], Bt[0][1], a2, c2, 64, invE);
    aggregate_kernel<64><<<AGG, 256>>>(t2, rowptr, eidx, a2, c2, hA, n);

    // ---- layer 2: 64 -> 128 ----
    cudaMemsetAsync(stats, 0, 1024 * sizeof(float));
    gemm_kernel<128, 64, 128, true><<<dim3(EB, 2), 256>>>(
        hA, srcp, dstp, nullptr, nullptr, W[1][0], B[1][0], t1, sum1, sq1, E);
    finalize_kernel<<<1, 128>>>(sum1, sq1, Gm[1][0], Bt[1][0], a1, c1, 128, invE);
    gemm_kernel<128, 0, 128, false><<<dim3(EB, 2), 256>>>(
        t1, nullptr, nullptr, a1, c1, W[1][1], B[1][1], t2, sum2, sq2, E);
    finalize_kernel<<<1, 128>>>(sum2, sq2, Gm[1][1], Bt[1][1], a2, c2, 128, invE);
    aggregate_kernel<128><<<AGG, 256>>>(t2, rowptr, eidx, a2, c2, hB, n);

    // ---- layer 3: 128 -> 256 ----
    cudaMemsetAsync(stats, 0, 1024 * sizeof(float));
    gemm_kernel<256, 128, 256, true><<<dim3(EB, 4), 256>>>(
        hB, srcp, dstp, nullptr, nullptr, W[2][0], B[2][0], t1, sum1, sq1, E);
    finalize_kernel<<<1, 256>>>(sum1, sq1, Gm[2][0], Bt[2][0], a1, c1, 256, invE);
    gemm_kernel<256, 0, 256, false><<<dim3(EB, 4), 256>>>(
        t1, nullptr, nullptr, a1, c1, W[2][1], B[2][1], t2, sum2, sq2, E);
    finalize_kernel<<<1, 256>>>(sum2, sq2, Gm[2][1], Bt[2][1], a2, c2, 256, invE);
    aggregate_kernel<256><<<AGG, 256>>>(t2, rowptr, eidx, a2, c2, hA, n);

    // ---- pool + head ----
    pool_kernel<<<GG, 256>>>(hA, gstart, pool);
    head1_kernel<<<GG, 128>>>(pool, hW1, hb1, zbuf);
    head2_kernel<<<1, 128>>>(zbuf, hW2, hb2, (float*)d_out);
}

// round 3
// speedup vs baseline: 1.8504x; 1.8504x over previous
#include <cuda_runtime.h>
#include <cuda_bf16.h>
#include <cstdint>

// ---------------- problem constants ----------------
#define NN 50000
#define EE 500000
#define GG 64

// ---------------- scratch (device globals; no allocation allowed) ----------
__device__ float g_t1[(size_t)EE * 256];     // 512 MB  edge intermediate 1
__device__ float g_t2[(size_t)EE * 256];     // 512 MB  edge intermediate 2
__device__ float g_hA[(size_t)NN * 256];     // node features ping
__device__ float g_hB[(size_t)NN * 256];     // node features pong
__device__ float g_stats[1024];              // sum1[256], sq1[256], sum2[256], sq2[256]
__device__ float g_norm[1024];               // a1[256], c1[256], a2[256], c2[256]
__device__ int   g_deg[NN];
__device__ int   g_rowptr[NN + 1];
__device__ int   g_cursor[NN];
__device__ int   g_eidx[EE];
__device__ int   g_cnt[GG];
__device__ int   g_gstart[GG + 1];
__device__ float g_pool[GG * 256];
__device__ float g_zbuf[GG * 128];
// transposed bf16 hi/lo weights (Wt[OC][KPAD]) for all 6 GEMMs
__device__ __nv_bfloat16 g_wth[172032];
__device__ __nv_bfloat16 g_wtl[172032];

// ---------------- mma.sync helper (sm_80+ PTX; works on plain sm_103) ------
#define MMA_BF16(d, a, b)                                                        \
    asm volatile("mma.sync.aligned.m16n8k16.row.col.f32.bf16.bf16.f32 "          \
                 "{%0,%1,%2,%3}, {%4,%5,%6,%7}, {%8,%9}, {%0,%1,%2,%3};"         \
                 : "+f"((d)[0]), "+f"((d)[1]), "+f"((d)[2]), "+f"((d)[3])        \
                 : "r"((a)[0]), "r"((a)[1]), "r"((a)[2]), "r"((a)[3]),           \
                   "r"((b)[0]), "r"((b)[1]))

// ---------------- CSR build ----------------
__global__ void hist_deg_kernel(const int* __restrict__ dst, int* __restrict__ deg, int E) {
    int e = blockIdx.x * blockDim.x + threadIdx.x;
    if (e < E) atomicAdd(&deg[dst[e]], 1);
}
__global__ void hist_cnt_kernel(const int* __restrict__ batch, int* __restrict__ cnt, int n) {
    int i = blockIdx.x * blockDim.x + threadIdx.x;
    if (i < n) atomicAdd(&cnt[batch[i]], 1);
}
__global__ void scan_kernel(const int* __restrict__ deg, int* __restrict__ rowptr,
                            int* __restrict__ cursor, const int* __restrict__ cnt,
                            int* __restrict__ gstart, int n) {
    __shared__ int sh[1024];
    __shared__ int carry;
    int t = threadIdx.x;
    if (t == 0) carry = 0;
    __syncthreads();
    for (int base = 0; base < n; base += 1024) {
        int idx = base + t;
        int v = (idx < n) ? deg[idx] : 0;
        sh[t] = v;
        __syncthreads();
        for (int off = 1; off < 1024; off <<= 1) {
            int add = (t >= off) ? sh[t - off] : 0;
            __syncthreads();
            sh[t] += add;
            __syncthreads();
        }
        int ex = sh[t] - v;
        int cbase = carry;
        if (idx < n) { rowptr[idx] = cbase + ex; cursor[idx] = cbase + ex; }
        __syncthreads();
        if (t == 1023) carry = cbase + sh[1023];
        __syncthreads();
    }
    if (t == 0) {
        rowptr[n] = carry;
        int s = 0;
        for (int g = 0; g < GG; g++) { gstart[g] = s; s += cnt[g]; }
        gstart[GG] = s;
    }
}
__global__ void fill_csr_kernel(const int* __restrict__ dst, int* __restrict__ cursor,
                                int* __restrict__ eidx, int E) {
    int e = blockIdx.x * blockDim.x + threadIdx.x;
    if (e < E) {
        int p = atomicAdd(&cursor[dst[e]], 1);
        eidx[p] = e;
    }
}

// ---------------- weight convert: W[K,OC] fp32 -> Wt[OC][KPAD] bf16 hi/lo ---
__global__ void convert_w_kernel(const float* __restrict__ W,
                                 __nv_bfloat16* __restrict__ Wth,
                                 __nv_bfloat16* __restrict__ Wtl,
                                 int K, int OC, int KPAD) {
    int idx = blockIdx.x * blockDim.x + threadIdx.x;
    if (idx >= OC * KPAD) return;
    int n = idx / KPAD, k = idx % KPAD;
    float w = (k < K) ? W[(size_t)k * OC + n] : 0.f;
    __nv_bfloat16 h = __float2bfloat16_rn(w);
    Wth[idx] = h;
    Wtl[idx] = __float2bfloat16_rn(w - __bfloat162float(h));
}

// ---------------- tensor-core GEMM via mma.sync (bf16 hi/lo split) ---------
// out[e, 0:OC] = A[e, 0:K] @ W[K, OC] + bias   (fp32 accumulate)
// GATHER=true : A[e,k] = k<C ? feat[dst,k] : feat[src,k-C]-feat[dst,k-C]
// GATHER=false: A[e,k] = relu(t[e,k]*an[k] + cn[k])
// Block tile: 128 x BN.  8 warps = 4(M) x 2(N).  Warp tile: 32 x BN/2.
// K processed in chunks of 32 staged in smem with stride 40 bf16 (conflict-free).
template <int C, int K, int OC, int BN, bool GATHER>
__global__ __launch_bounds__(256)
void mgemm_kernel(const float* __restrict__ feats,
                  const int* __restrict__ src, const int* __restrict__ dst,
                  const float* __restrict__ an, const float* __restrict__ cn,
                  const __nv_bfloat16* __restrict__ Wth,
                  const __nv_bfloat16* __restrict__ Wtl,
                  const float* __restrict__ bias,
                  float* __restrict__ out, int E) {
    constexpr int KPAD = (K + 31) / 32 * 32;
    constexpr int NCH = KPAD / 32;
    constexpr int NT = BN / 16;          // n8-tiles per warp (warp N = BN/2)
    constexpr int SAS = 40;              // smem stride in bf16

    __shared__ __nv_bfloat16 sAh[128 * SAS], sAl[128 * SAS];
    __shared__ __nv_bfloat16 sBh[BN * SAS], sBl[BN * SAS];
    __shared__ int sdst[128], ssrc[128];

    const int tid = threadIdx.x;
    const int lane = tid & 31;
    const int wid = tid >> 5;
    const int wm = wid & 3;              // 0..3 over M
    const int wn = wid >> 2;             // 0..1 over N
    const int e0 = blockIdx.x * 128;
    const int col0 = blockIdx.y * BN;

    if (GATHER && tid < 128) {
        int e = e0 + tid;
        int ee = (e < E) ? e : (E - 1);
        sdst[tid] = dst[ee];
        ssrc[tid] = src[ee];
    }
    __syncthreads();

    float acc[2][NT][4];
#pragma unroll
    for (int mt = 0; mt < 2; mt++)
#pragma unroll
        for (int nt = 0; nt < NT; nt++)
#pragma unroll
            for (int j = 0; j < 4; j++) acc[mt][nt][j] = 0.f;

    const int arow = tid >> 1;           // A production: row handled
    const int acg = (tid & 1) * 16;      // 16 cols within 32-col chunk

    for (int ch = 0; ch < NCH; ch++) {
        // ---- produce A chunk (128 x 32), hi/lo split ----
        {
            int nd = 0, ns = 0;
            if (GATHER) { nd = sdst[arow]; ns = ssrc[arow]; }
            const int e = e0 + arow;
#pragma unroll
            for (int u = 0; u < 4; u++) {
                const int k = ch * 32 + acg + u * 4;
                float4 v;
                if (GATHER) {
                    if (C % 4 == 0) {
                        if (k < C) {
                            v = *reinterpret_cast<const float4*>(&feats[(size_t)nd * C + k]);
                        } else {
                            float4 xs = *reinterpret_cast<const float4*>(&feats[(size_t)ns * C + (k - C)]);
                            float4 xd = *reinterpret_cast<const float4*>(&feats[(size_t)nd * C + (k - C)]);
                            v = make_float4(xs.x - xd.x, xs.y - xd.y, xs.z - xd.z, xs.w - xd.w);
                        }
                    } else {  // scalar path (C=7, K=14, KPAD=32)
                        float t[4];
#pragma unroll
                        for (int j = 0; j < 4; j++) {
                            int kk = k + j;
                            if (kk < C) t[j] = feats[(size_t)nd * C + kk];
                            else if (kk < K) t[j] = feats[(size_t)ns * C + (kk - C)] - feats[(size_t)nd * C + (kk - C)];
                            else t[j] = 0.f;
                        }
                        v = make_float4(t[0], t[1], t[2], t[3]);
                    }
                } else {
                    if (e < E) {
                        float4 t = *reinterpret_cast<const float4*>(&feats[(size_t)e * K + k]);
                        v.x = fmaxf(t.x * an[k + 0] + cn[k + 0], 0.f);
                        v.y = fmaxf(t.y * an[k + 1] + cn[k + 1], 0.f);
                        v.z = fmaxf(t.z * an[k + 2] + cn[k + 2], 0.f);
                        v.w = fmaxf(t.w * an[k + 3] + cn[k + 3], 0.f);
                    } else {
                        v = make_float4(0.f, 0.f, 0.f, 0.f);
                    }
                }
                __nv_bfloat162 h01 = __float22bfloat162_rn(make_float2(v.x, v.y));
                __nv_bfloat162 h23 = __float22bfloat162_rn(make_float2(v.z, v.w));
                float2 hf01 = __bfloat1622float2(h01);
                float2 hf23 = __bfloat1622float2(h23);
                __nv_bfloat162 l01 = __float22bfloat162_rn(make_float2(v.x - hf01.x, v.y - hf01.y));
                __nv_bfloat162 l23 = __float22bfloat162_rn(make_float2(v.z - hf23.x, v.w - hf23.y));
                uint2 H, L;
                H.x = *reinterpret_cast<uint32_t*>(&h01);
                H.y = *reinterpret_cast<uint32_t*>(&h23);
                L.x = *reinterpret_cast<uint32_t*>(&l01);
                L.y = *reinterpret_cast<uint32_t*>(&l23);
                int so = arow * SAS + acg + u * 4;
                *reinterpret_cast<uint2*>(&sAh[so]) = H;
                *reinterpret_cast<uint2*>(&sAl[so]) = L;
            }
        }
        // ---- load B chunk (BN x 32) ----
        {
#pragma unroll
            for (int i = tid; i < BN * 4; i += 256) {
                int n = i >> 2, u = i & 3;
                size_t soff = (size_t)(col0 + n) * KPAD + ch * 32 + u * 8;
                int doff = n * SAS + u * 8;
                *reinterpret_cast<uint4*>(&sBh[doff]) =
                    *reinterpret_cast<const uint4*>(Wth + soff);
                *reinterpret_cast<uint4*>(&sBl[doff]) =
                    *reinterpret_cast<const uint4*>(Wtl + soff);
            }
        }
        __syncthreads();

        // ---- 2 x k16 MMA steps ----
#pragma unroll
        for (int ks = 0; ks < 2; ks++) {
            const int kb = ks * 16;
            uint32_t ah[2][4], al[2][4];
            const int ar = wm * 32 + (lane >> 2);
            const int ac = kb + (lane & 3) * 2;
#pragma unroll
            for (int mt = 0; mt < 2; mt++) {
                int r = ar + mt * 16;
                ah[mt][0] = *reinterpret_cast<const uint32_t*>(&sAh[r * SAS + ac]);
                ah[mt][1] = *reinterpret_cast<const uint32_t*>(&sAh[(r + 8) * SAS + ac]);
                ah[mt][2] = *reinterpret_cast<const uint32_t*>(&sAh[r * SAS + ac + 8]);
                ah[mt][3] = *reinterpret_cast<const uint32_t*>(&sAh[(r + 8) * SAS + ac + 8]);
                al[mt][0] = *reinterpret_cast<const uint32_t*>(&sAl[r * SAS + ac]);
                al[mt][1] = *reinterpret_cast<const uint32_t*>(&sAl[(r + 8) * SAS + ac]);
                al[mt][2] = *reinterpret_cast<const uint32_t*>(&sAl[r * SAS + ac + 8]);
                al[mt][3] = *reinterpret_cast<const uint32_t*>(&sAl[(r + 8) * SAS + ac + 8]);
            }
            uint32_t bh[NT][2], bl[NT][2];
#pragma unroll
            for (int nt = 0; nt < NT; nt++) {
                int nn = wn * (BN / 2) + nt * 8 + (lane >> 2);
                int bc = kb + (lane & 3) * 2;
                bh[nt][0] = *reinterpret_cast<const uint32_t*>(&sBh[nn * SAS + bc]);
                bh[nt][1] = *reinterpret_cast<const uint32_t*>(&sBh[nn * SAS + bc + 8]);
                bl[nt][0] = *reinterpret_cast<const uint32_t*>(&sBl[nn * SAS + bc]);
                bl[nt][1] = *reinterpret_cast<const uint32_t*>(&sBl[nn * SAS + bc + 8]);
            }
#pragma unroll
            for (int mt = 0; mt < 2; mt++)
#pragma unroll
                for (int nt = 0; nt < NT; nt++) {
                    MMA_BF16(acc[mt][nt], ah[mt], bh[nt]);
                    MMA_BF16(acc[mt][nt], ah[mt], bl[nt]);
                    MMA_BF16(acc[mt][nt], al[mt], bh[nt]);
                }
        }
        __syncthreads();
    }

    // ---- epilogue: bias + store ----
#pragma unroll
    for (int mt = 0; mt < 2; mt++) {
        int r = wm * 32 + mt * 16 + (lane >> 2);
        int e1 = e0 + r;
        int e2 = e0 + r + 8;
#pragma unroll
        for (int nt = 0; nt < NT; nt++) {
            int col = col0 + wn * (BN / 2) + nt * 8 + (lane & 3) * 2;
            float b0 = bias[col], b1 = bias[col + 1];
            if (e1 < E) {
                float2 o = make_float2(acc[mt][nt][0] + b0, acc[mt][nt][1] + b1);
                *reinterpret_cast<float2*>(&out[(size_t)e1 * OC + col]) = o;
            }
            if (e2 < E) {
                float2 o = make_float2(acc[mt][nt][2] + b0, acc[mt][nt][3] + b1);
                *reinterpret_cast<float2*>(&out[(size_t)e2 * OC + col]) = o;
            }
        }
    }
}

// ---------------- column stats over t[E, OC] ----------------
template <int OC>
__global__ __launch_bounds__(256)
void stats_kernel(const float* __restrict__ t, float* __restrict__ sum,
                  float* __restrict__ sq, int E) {
    constexpr int TPR = OC / 4;          // threads per row
    constexpr int RPB = 256 / TPR;       // rows per block pass
    __shared__ float ss[OC], sv[OC];
    const int tid = threadIdx.x;
    for (int i = tid; i < OC; i += 256) { ss[i] = 0.f; sv[i] = 0.f; }
    __syncthreads();
    const int cg = (tid % TPR) * 4;
    const int r0 = tid / TPR;
    float4 s = make_float4(0, 0, 0, 0), q = make_float4(0, 0, 0, 0);
    for (int row = blockIdx.x * RPB + r0; row < E; row += gridDim.x * RPB) {
        float4 v = *reinterpret_cast<const float4*>(&t[(size_t)row * OC + cg]);
        s.x += v.x; s.y += v.y; s.z += v.z; s.w += v.w;
        q.x += v.x * v.x; q.y += v.y * v.y; q.z += v.z * v.z; q.w += v.w * v.w;
    }
    atomicAdd(&ss[cg + 0], s.x); atomicAdd(&ss[cg + 1], s.y);
    atomicAdd(&ss[cg + 2], s.z); atomicAdd(&ss[cg + 3], s.w);
    atomicAdd(&sv[cg + 0], q.x); atomicAdd(&sv[cg + 1], q.y);
    atomicAdd(&sv[cg + 2], q.z); atomicAdd(&sv[cg + 3], q.w);
    __syncthreads();
    for (int i = tid; i < OC; i += 256) {
        atomicAdd(&sum[i], ss[i]);
        atomicAdd(&sq[i], sv[i]);
    }
}

// ---------------- BN finalize ----------------
__global__ void finalize_kernel(const float* __restrict__ sum, const float* __restrict__ sq,
                                const float* __restrict__ gamma, const float* __restrict__ beta,
                                float* __restrict__ a, float* __restrict__ c,
                                int OC, float invE) {
    int i = blockIdx.x * blockDim.x + threadIdx.x;
    if (i < OC) {
        float m = sum[i] * invE;
        float var = sq[i] * invE - m * m;
        float rs = rsqrtf(var + 1e-5f);
        float ai = gamma[i] * rs;
        a[i] = ai;
        c[i] = beta[i] - m * ai;
    }
}

// ---------------- normalize + relu + mean-aggregate (CSR, warp per node) ----
template <int OC>
__global__ __launch_bounds__(256)
void aggregate_kernel(const float* __restrict__ t, const int* __restrict__ rowptr,
                      const int* __restrict__ eidx, const float* __restrict__ a,
                      const float* __restrict__ c, float* __restrict__ hout, int n) {
    int warp = (blockIdx.x * blockDim.x + threadIdx.x) >> 5;
    int lane = threadIdx.x & 31;
    if (warp >= n) return;
    constexpr int R = OC / 32;
    float av[R], cv[R], acc[R];
#pragma unroll
    for (int j = 0; j < R; j++) {
        int ch = j * 32 + lane;
        av[j] = a[ch]; cv[j] = c[ch]; acc[j] = 0.f;
    }
    int beg = rowptr[warp], end = rowptr[warp + 1];
    for (int p = beg; p < end; p++) {
        int e = eidx[p];
        const float* rowp = t + (size_t)e * OC;
#pragma unroll
        for (int j = 0; j < R; j++) {
            float v = rowp[j * 32 + lane];
            acc[j] += fmaxf(v * av[j] + cv[j], 0.f);
        }
    }
    float inv = 1.f / fmaxf((float)(end - beg), 1.f);
#pragma unroll
    for (int j = 0; j < R; j++) hout[(size_t)warp * OC + j * 32 + lane] = acc[j] * inv;
}

// ---------------- global mean pool + head ----------------
__global__ void pool_kernel(const float* __restrict__ h, const int* __restrict__ gstart,
                            float* __restrict__ pool) {
    int g = blockIdx.x;
    int ch = threadIdx.x;
    int beg = gstart[g], end = gstart[g + 1];
    float s = 0.f;
    for (int nidx = beg; nidx < end; nidx++) s += h[(size_t)nidx * 256 + ch];
    pool[g * 256 + ch] = s / fmaxf((float)(end - beg), 1.f);
}
__global__ void head1_kernel(const float* __restrict__ pool, const float* __restrict__ W,
                             const float* __restrict__ b, float* __restrict__ z) {
    int g = blockIdx.x, j = threadIdx.x;
    __shared__ float sp[256];
    sp[j] = pool[g * 256 + j];
    sp[j + 128] = pool[g * 256 + j + 128];
    __syncthreads();
    float s = b[j];
#pragma unroll 8
    for (int k = 0; k < 256; k++) s += sp[k] * W[k * 128 + j];
    z[g * 128 + j] = fmaxf(s, 0.f);
}
__global__ void head2_kernel(const float* __restrict__ z, const float* __restrict__ W,
                             const float* __restrict__ b, float* __restrict__ out) {
    int t = threadIdx.x;
    int g = t >> 1, j = t & 1;
    float s = b[j];
#pragma unroll 8
    for (int k = 0; k < 128; k++) s += z[g * 128 + k] * W[k * 2 + j];
    out[g * 2 + j] = s;
}

// ---------------- launch ----------------
extern "C" void kernel_launch(void* const* d_in, const int* in_sizes, int n_in,
                              void* d_out, int out_size) {
    const float* x     = (const float*)d_in[0];
    const int*   ei    = (const int*)d_in[1];
    const int*   batch = (const int*)d_in[2];

    const int E = in_sizes[1] / 2;
    const int n = in_sizes[2];
    const int* srcp = ei;
    const int* dstp = ei + E;

    const float* W[3][2];  const float* B[3][2];
    const float* Gm[3][2]; const float* Bt[3][2];
    for (int l = 0; l < 3; l++) {
        int base = 3 + l * 8;
        W[l][0]  = (const float*)d_in[base + 0];
        B[l][0]  = (const float*)d_in[base + 1];
        Gm[l][0] = (const float*)d_in[base + 2];
        Bt[l][0] = (const float*)d_in[base + 3];
        W[l][1]  = (const float*)d_in[base + 4];
        B[l][1]  = (const float*)d_in[base + 5];
        Gm[l][1] = (const float*)d_in[base + 6];
        Bt[l][1] = (const float*)d_in[base + 7];
    }
    const float* hW1 = (const float*)d_in[27];
    const float* hb1 = (const float*)d_in[28];
    const float* hW2 = (const float*)d_in[29];
    const float* hb2 = (const float*)d_in[30];

    float *t1, *t2, *hA, *hB, *stats, *norm, *pool, *zbuf;
    int *deg, *rowptr, *cursor, *eidx, *cnt, *gstart;
    __nv_bfloat16 *wth, *wtl;
    cudaGetSymbolAddress((void**)&t1, g_t1);
    cudaGetSymbolAddress((void**)&t2, g_t2);
    cudaGetSymbolAddress((void**)&hA, g_hA);
    cudaGetSymbolAddress((void**)&hB, g_hB);
    cudaGetSymbolAddress((void**)&stats, g_stats);
    cudaGetSymbolAddress((void**)&norm, g_norm);
    cudaGetSymbolAddress((void**)&deg, g_deg);
    cudaGetSymbolAddress((void**)&rowptr, g_rowptr);
    cudaGetSymbolAddress((void**)&cursor, g_cursor);
    cudaGetSymbolAddress((void**)&eidx, g_eidx);
    cudaGetSymbolAddress((void**)&cnt, g_cnt);
    cudaGetSymbolAddress((void**)&gstart, g_gstart);
    cudaGetSymbolAddress((void**)&pool, g_pool);
    cudaGetSymbolAddress((void**)&zbuf, g_zbuf);
    cudaGetSymbolAddress((void**)&wth, g_wth);
    cudaGetSymbolAddress((void**)&wtl, g_wtl);

    float* sum1 = stats + 0;   float* sq1 = stats + 256;
    float* sum2 = stats + 512; float* sq2 = stats + 768;
    float* a1 = norm + 0;   float* c1 = norm + 256;
    float* a2 = norm + 512; float* c2 = norm + 768;

    // transposed weight buffers: {L1g1(64x32), L1g2(64x64), L2g1(128x128),
    //                             L2g2(128x128), L3g1(256x256), L3g2(256x256)}
    const int wt_off[6] = {0, 2048, 6144, 22528, 38912, 104448};

    const float invE = 1.f / (float)E;
    const int EB = (E + 127) / 128;
    const int EG = (E + 255) / 256;
    const int NG = (n + 255) / 256;
    const int AGG = (n * 32 + 255) / 256;
    const int SGRID = 592;

    // ---- CSR build + weight conversion ----
    cudaMemsetAsync(deg, 0, n * sizeof(int));
    cudaMemsetAsync(cnt, 0, GG * sizeof(int));
    hist_deg_kernel<<<EG, 256>>>(dstp, deg, E);
    hist_cnt_kernel<<<NG, 256>>>(batch, cnt, n);
    scan_kernel<<<1, 1024>>>(deg, rowptr, cursor, cnt, gstart, n);
    fill_csr_kernel<<<EG, 256>>>(dstp, cursor, eidx, E);

    convert_w_kernel<<<(64 * 32 + 255) / 256, 256>>>(W[0][0], wth + wt_off[0], wtl + wt_off[0], 14, 64, 32);
    convert_w_kernel<<<(64 * 64 + 255) / 256, 256>>>(W[0][1], wth + wt_off[1], wtl + wt_off[1], 64, 64, 64);
    convert_w_kernel<<<(128 * 128 + 255) / 256, 256>>>(W[1][0], wth + wt_off[2], wtl + wt_off[2], 128, 128, 128);
    convert_w_kernel<<<(128 * 128 + 255) / 256, 256>>>(W[1][1], wth + wt_off[3], wtl + wt_off[3], 128, 128, 128);
    convert_w_kernel<<<(256 * 256 + 255) / 256, 256>>>(W[2][0], wth + wt_off[4], wtl + wt_off[4], 256, 256, 256);
    convert_w_kernel<<<(256 * 256 + 255) / 256, 256>>>(W[2][1], wth + wt_off[5], wtl + wt_off[5], 256, 256, 256);

    // ---- layer 1: 7 -> 64 ----
    cudaMemsetAsync(stats, 0, 1024 * sizeof(float));
    mgemm_kernel<7, 14, 64, 64, true><<<dim3(EB, 1), 256>>>(
        x, srcp, dstp, nullptr, nullptr, wth + wt_off[0], wtl + wt_off[0], B[0][0], t1, E);
    stats_kernel<64><<<SGRID, 256>>>(t1, sum1, sq1, E);
    finalize_kernel<<<1, 64>>>(sum1, sq1, Gm[0][0], Bt[0][0], a1, c1, 64, invE);
    mgemm_kernel<0, 64, 64, 64, false><<<dim3(EB, 1), 256>>>(
        t1, nullptr, nullptr, a1, c1, wth + wt_off[1], wtl + wt_off[1], B[0][1], t2, E);
    stats_kernel<64><<<SGRID, 256>>>(t2, sum2, sq2, E);
    finalize_kernel<<<1, 64>>>(sum2, sq2, Gm[0][1], Bt[0][1], a2, c2, 64, invE);
    aggregate_kernel<64><<<AGG, 256>>>(t2, rowptr, eidx, a2, c2, hA, n);

    // ---- layer 2: 64 -> 128 ----
    cudaMemsetAsync(stats, 0, 1024 * sizeof(float));
    mgemm_kernel<64, 128, 128, 128, true><<<dim3(EB, 1), 256>>>(
        hA, srcp, dstp, nullptr, nullptr, wth + wt_off[2], wtl + wt_off[2], B[1][0], t1, E);
    stats_kernel<128><<<SGRID, 256>>>(t1, sum1, sq1, E);
    finalize_kernel<<<1, 128>>>(sum1, sq1, Gm[1][0], Bt[1][0], a1, c1, 128, invE);
    mgemm_kernel<0, 128, 128, 128, false><<<dim3(EB, 1), 256>>>(
        t1, nullptr, nullptr, a1, c1, wth + wt_off[3], wtl + wt_off[3], B[1][1], t2, E);
    stats_kernel<128><<<SGRID, 256>>>(t2, sum2, sq2, E);
    finalize_kernel<<<1, 128>>>(sum2, sq2, Gm[1][1], Bt[1][1], a2, c2, 128, invE);
    aggregate_kernel<128><<<AGG, 256>>>(t2, rowptr, eidx, a2, c2, hB, n);

    // ---- layer 3: 128 -> 256 ----
    cudaMemsetAsync(stats, 0, 1024 * sizeof(float));
    mgemm_kernel<128, 256, 256, 128, true><<<dim3(EB, 2), 256>>>(
        hB, srcp, dstp, nullptr, nullptr, wth + wt_off[4], wtl + wt_off[4], B[2][0], t1, E);
    stats_kernel<256><<<SGRID, 256>>>(t1, sum1, sq1, E);
    finalize_kernel<<<1, 256>>>(sum1, sq1, Gm[2][0], Bt[2][0], a1, c1, 256, invE);
    mgemm_kernel<0, 256, 256, 128, false><<<dim3(EB, 2), 256>>>(
        t1, nullptr, nullptr, a1, c1, wth + wt_off[5], wtl + wt_off[5], B[2][1], t2, E);
    stats_kernel<256><<<SGRID, 256>>>(t2, sum2, sq2, E);
    finalize_kernel<<<1, 256>>>(sum2, sq2, Gm[2][1], Bt[2][1], a2, c2, 256, invE);
    aggregate_kernel<256><<<AGG, 256>>>(t2, rowptr, eidx, a2, c2, hA, n);

    // ---- pool + head ----
    pool_kernel<<<GG, 256>>>(hA, gstart, pool);
    head1_kernel<<<GG, 128>>>(pool, hW1, hb1, zbuf);
    head2_kernel<<<1, 128>>>(zbuf, hW2, hb2, (float*)d_out);
}